// round 12
// baseline (speedup 1.0000x reference)
#include <cuda_runtime.h>
#include <cuda_bf16.h>
#include <math.h>
#include <stdint.h>

#define SEQ 512

typedef unsigned int u32;
typedef unsigned long long u64;

// ---------------- device globals (no cudaMalloc allowed) ----------------
// quantized integer-valued weights (bf16-exact), layout gW[k*768 + c], c = gate*256 + j
__device__ float gW1x[256 * 768];
__device__ float gW1h[256 * 768];
__device__ float gW2i[256 * 768];
__device__ float gW2h[256 * 768];

// activations as bf16 hi/lo planes, [b][k] row-major
__device__ __nv_bfloat16 g_xhi[(size_t)SEQ * 65536];
__device__ __nv_bfloat16 g_xlo[(size_t)SEQ * 65536];
// h1: depth-4 ring (L1 may run up to 3 phases ahead of L2)
__device__ __nv_bfloat16 g_h1hi[4][65536];
__device__ __nv_bfloat16 g_h1lo[4][65536];
// h2: parity double buffer
__device__ __nv_bfloat16 g_h2hi[2][65536];
__device__ __nv_bfloat16 g_h2lo[2][65536];

__device__ float g_scale[4];
// per-batch-tile progress counters (padded to 128B each)
__device__ unsigned g_ctrL1[4 * 32];
__device__ unsigned g_ctrL2[4 * 32];

// ---------------- helpers ----------------
__device__ __forceinline__ u32 smem_u32(const void* p) {
    u32 a;
    asm("{ .reg .u64 t; cvta.to.shared.u64 t, %1; cvt.u32.u64 %0, t; }" : "=r"(a) : "l"(p));
    return a;
}

#define LDMATRIX4(r, a) \
    asm volatile("ldmatrix.sync.aligned.m8n8.x4.shared.b16 {%0,%1,%2,%3}, [%4];" \
        : "=r"((r)[0]), "=r"((r)[1]), "=r"((r)[2]), "=r"((r)[3]) : "r"(a))

#define MMA16816(d, a, b0, b1) \
    asm volatile("mma.sync.aligned.m16n8k16.row.col.f32.bf16.bf16.f32 " \
        "{%0,%1,%2,%3}, {%4,%5,%6,%7}, {%8,%9}, {%0,%1,%2,%3};" \
        : "+f"((d)[0]), "+f"((d)[1]), "+f"((d)[2]), "+f"((d)[3]) \
        : "r"((a)[0]), "r"((a)[1]), "r"((a)[2]), "r"((a)[3]), "r"(b0), "r"(b1))

#define LDS64(r0, r1, a) \
    asm volatile("ld.shared.v2.b32 {%0,%1}, [%2];" : "=r"(r0), "=r"(r1) : "r"(a))

#define LDS32(r0, a) \
    asm volatile("ld.shared.b32 %0, [%1];" : "=r"(r0) : "r"(a))

#define CPA16(dst, src) \
    asm volatile("cp.async.cg.shared.global [%0], [%1], 16;" :: "r"(dst), "l"(src) : "memory")
#define CPA_COMMIT() asm volatile("cp.async.commit_group;" ::: "memory")
#define CPA_WAIT(N)  asm volatile("cp.async.wait_group %0;" :: "n"(N) : "memory")

__device__ __forceinline__ u32 pkbf(float x, float y) {
    __nv_bfloat162 t = __floats2bfloat162_rn(x, y);
    return *(u32*)&t;
}

__device__ __forceinline__ float sigf(float x) { return 1.f / (1.f + expf(-x)); }

// ---------------- setup kernels ----------------
__global__ void k_init(const float* __restrict__ h1, const float* __restrict__ h2) {
    int i = blockIdx.x * blockDim.x + threadIdx.x;
    if (i < 128) { g_ctrL1[i] = 0u; g_ctrL2[i] = 0u; }
    if (i < 65536) {
        float v1 = h1[i], v2 = h2[i];
        __nv_bfloat16 a = __float2bfloat16(v1);
        g_h1hi[0][i] = a;                                     // h1(0) -> ring slot 0
        g_h1lo[0][i] = __float2bfloat16(v1 - __bfloat162float(a));
        __nv_bfloat16 b = __float2bfloat16(v2);
        g_h2hi[1][i] = b;                                     // h2(0) -> parity slot 1 (read at p=1)
        g_h2lo[1][i] = __float2bfloat16(v2 - __bfloat162float(b));
    }
}

__global__ void k_scales(const float* __restrict__ w0, const float* __restrict__ w1,
                         const float* __restrict__ w2, const float* __restrict__ w3) {
    const float* w = (blockIdx.x == 0) ? w0 : (blockIdx.x == 1) ? w1
                   : (blockIdx.x == 2) ? w2 : w3;
    const int n = 768 * 256;
    float m = 0.f;
    for (int i = threadIdx.x; i < n; i += blockDim.x) m = fmaxf(m, fabsf(w[i]));
    __shared__ float sm[512];
    sm[threadIdx.x] = m;
    __syncthreads();
    for (int s = blockDim.x >> 1; s > 0; s >>= 1) {
        if (threadIdx.x < s) sm[threadIdx.x] = fmaxf(sm[threadIdx.x], sm[threadIdx.x + s]);
        __syncthreads();
    }
    if (threadIdx.x == 0) g_scale[blockIdx.x] = sm[0] / 127.0f;
}

// gW[k*768 + c] = rint(W[c*256 + k] / s)   (c = gate*256 + j; |v| <= 127, bf16-exact)
__global__ void k_pack(const float* __restrict__ wih1, const float* __restrict__ whh1,
                       const float* __restrict__ wih2, const float* __restrict__ whh2) {
    const float s0 = g_scale[0], s1 = g_scale[1], s2 = g_scale[2], s3 = g_scale[3];
    const int N = 256 * 768;
    for (int i = blockIdx.x * blockDim.x + threadIdx.x; i < N;
         i += gridDim.x * blockDim.x) {
        int k = i / 768, c = i - k * 768;
        int off = c * 256 + k;
        gW1x[i] = rintf(wih1[off] / s0);
        gW1h[i] = rintf(whh1[off] / s1);
        gW2i[i] = rintf(wih2[off] / s2);
        gW2h[i] = rintf(whh2[off] / s3);
    }
}

// x -> bf16 hi/lo planes
__global__ void k_convx(const float* __restrict__ x) {
    size_t i = ((size_t)blockIdx.x * blockDim.x + threadIdx.x) * 4;
    if (i >= (size_t)SEQ * 65536) return;
    float4 v = *(const float4*)(x + i);
    float vv[4] = {v.x, v.y, v.z, v.w};
    __nv_bfloat16 hi[4], lo[4];
    #pragma unroll
    for (int r = 0; r < 4; ++r) {
        hi[r] = __float2bfloat16(vv[r]);
        lo[r] = __float2bfloat16(vv[r] - __bfloat162float(hi[r]));
    }
    *(uint2*)(g_xhi + i) = *(uint2*)hi;
    *(uint2*)(g_xlo + i) = *(uint2*)lo;
}

// ---------------- per-bt sync primitives ----------------
__device__ __forceinline__ void ctr_arrive(unsigned* c) {
    __syncthreads();
    if (threadIdx.x == 0) {
        __threadfence();
        atomicAdd(c, 1u);   // return unused -> RED
    }
}

__device__ __forceinline__ void ctr_wait2(const unsigned* c1, int t1,
                                          const unsigned* c2, int t2) {
    if (threadIdx.x == 0) {
        if (t1 > 0) while ((int)(*(volatile const unsigned*)c1) < t1) { }
        if (t2 > 0) while ((int)(*(volatile const unsigned*)c2) < t2) { }
        __threadfence();
    }
    __syncthreads();
}

// ---------------- main persistent kernel ----------------
// 128 CTAs x 256 threads. CTA 0..63 = layer1, 64..127 = layer2.
// CTA tile: M=64 batch rows x N=48 (GATE-MAJOR: n = gate*16 + jlocal).
// Warp grid 4M x 2N. Each warp: 3 n-tiles = gates r/z/n of its 8 j's.
// SMEM: bias @0, B frag stream @1024 (48KB), A planes @50176 (4 x 33792B).
#define S_BF   1024
#define S_A    50176
#define A_STR  528
#define A_PL   33792
#define SMEM_BYTES 185344

__global__ void __launch_bounds__(256) k_main(
    const float* __restrict__ b_ih1, const float* __restrict__ b_hh1,
    const float* __restrict__ b_ih2, const float* __restrict__ b_hh2,
    float* __restrict__ out)
{
    extern __shared__ char smem[];
    const u32 sbase = smem_u32(smem);
    float* sBias = (float*)smem;

    const int tid = threadIdx.x;
    const int ln = tid & 31, w = tid >> 5;
    const int wm = w & 3, wn = w >> 2;
    const int bid = blockIdx.x;
    const bool isL2 = bid >= 64;
    const int tb = isL2 ? bid - 64 : bid;
    const int bt = tb >> 4;
    const int b0 = bt * 64;
    const int j0 = (tb & 15) * 16;

    unsigned* ctr1 = &g_ctrL1[bt * 32];
    unsigned* ctr2 = &g_ctrL2[bt * 32];

    // ---- one-time: B fragment stream (2 src x 16 ksteps x 6 tiles x 32 lanes x 8B)
    {
        const int sB = w & 1;
        const float* Ws = sB ? (isL2 ? gW2h : gW1h) : (isL2 ? gW2i : gW1x);
        const int n = ln >> 2, kp = ln & 3;
        for (int ks = (w >> 1) * 4; ks < (w >> 1) * 4 + 4; ++ks) {
            #pragma unroll
            for (int tt = 0; tt < 6; ++tt) {
                int j = j0 + (tt & 1) * 8 + n;
                int c = (tt >> 1) * 256 + j;
                int k0 = ks * 16 + kp * 2;
                u32 f0 = pkbf(Ws[(size_t)k0 * 768 + c], Ws[(size_t)(k0 + 1) * 768 + c]);
                u32 f1 = pkbf(Ws[(size_t)(k0 + 8) * 768 + c], Ws[(size_t)(k0 + 9) * 768 + c]);
                u32 ad = sbase + S_BF + (u32)((((sB * 16 + ks) * 6 + tt) * 32 + ln) * 8);
                asm volatile("st.shared.v2.b32 [%0], {%1,%2};" :: "r"(ad), "r"(f0), "r"(f1) : "memory");
            }
        }
    }
    if (tid < 16) {
        int j = j0 + tid;
        const float* bi = isL2 ? b_ih2 : b_ih1;
        const float* bh = isL2 ? b_hh2 : b_hh1;
        sBias[tid * 4 + 0] = bi[j] + bh[j];
        sBias[tid * 4 + 1] = bi[j + 256] + bh[j + 256];
        sBias[tid * 4 + 2] = bi[j + 512];
        sBias[tid * 4 + 3] = bh[j + 512];
    }
    const float s_i = isL2 ? g_scale[2] : g_scale[0];
    const float s_h = isL2 ? g_scale[3] : g_scale[1];
    __syncthreads();

    // per-lane constants
    const int jb = j0 + wn * 8 + (ln & 3) * 2;        // global j of col pair
    const int b_r = b0 + wm * 16 + (ln >> 2);         // global batch row
    const int jl = wn * 8 + (ln & 3) * 2;
    float bR[2], bZ[2], bNi[2], bNh[2];
    #pragma unroll
    for (int cc = 0; cc < 2; ++cc) {
        bR[cc]  = sBias[(jl + cc) * 4 + 0];
        bZ[cc]  = sBias[(jl + cc) * 4 + 1];
        bNi[cc] = sBias[(jl + cc) * 4 + 2];
        bNh[cc] = sBias[(jl + cc) * 4 + 3];
    }
    const u32 a_base = sbase + S_A + (u32)(wm * 16 + (ln & 15)) * A_STR + (u32)((ln >> 4) * 16);
    // h_old via staged smem planes 2/3: lane's (row, j-pair)
    const u32 h_base = sbase + S_A + 2u * A_PL
                     + (u32)(wm * 16 + (ln >> 2)) * A_STR + (u32)(jb * 2);
    const int cp_row = tid >> 2;
    const int cp_seg = (tid & 3) * 64;

    // cp.async: two commit groups (kh halves) for one source (2 planes)
    #define ISSUE_SRC(PL_HI, PL_LO, PBASE) do { \
        _Pragma("unroll") \
        for (int kh = 0; kh < 2; ++kh) { \
            _Pragma("unroll") \
            for (int pq = 0; pq < 2; ++pq) { \
                const char* srcb = (const char*)((pq) ? (PL_LO) : (PL_HI)) \
                    + (size_t)(b0 + cp_row) * 512 + kh * 256 + cp_seg; \
                u32 dst = sbase + S_A + (u32)((PBASE) + pq) * A_PL \
                        + (u32)cp_row * A_STR + (u32)(kh * 256 + cp_seg); \
                _Pragma("unroll") \
                for (int i = 0; i < 4; ++i) CPA16(dst + i * 16, srcb + i * 16); \
            } \
            CPA_COMMIT(); \
        } \
    } while (0)

    #define DO_CHUNK(C, WAITN) do { \
        CPA_WAIT(WAITN); \
        __syncthreads(); \
        const int s = (C) >> 1, kh = (C) & 1; \
        _Pragma("unroll") \
        for (int k8 = 0; k8 < 8; ++k8) { \
            const int ks = kh * 8 + k8; \
            u32 a[2][4]; \
            _Pragma("unroll") \
            for (int q = 0; q < 2; ++q) \
                LDMATRIX4(a[q], a_base + (u32)(s * 2 + q) * A_PL + (u32)(ks * 32)); \
            _Pragma("unroll") \
            for (int g = 0; g < 3; ++g) { \
                u32 f0, f1; \
                u32 bad = sbase + S_BF \
                        + (u32)((((s * 16 + ks) * 6 + g * 2 + wn) * 32 + ln) * 8); \
                LDS64(f0, f1, bad); \
                if (s == 0) { \
                    MMA16816(acci[g], a[0], f0, f1); \
                    MMA16816(acci[g], a[1], f0, f1); \
                } else { \
                    MMA16816(acch[g], a[0], f0, f1); \
                    MMA16816(acch[g], a[1], f0, f1); \
                } \
            } \
        } \
    } while (0)

    // epilogue gate math (shared by both layers); reads h_old from smem planes 2/3
    #define GATE_EPI() do { \
        _Pragma("unroll") \
        for (int rh = 0; rh < 2; ++rh) { \
            u32 hw, lw; \
            LDS32(hw, h_base + (u32)(rh * 8) * A_STR); \
            LDS32(lw, h_base + (u32)(rh * 8) * A_STR + A_PL); \
            __nv_bfloat162 hv = *(__nv_bfloat162*)&hw; \
            __nv_bfloat162 lv = *(__nv_bfloat162*)&lw; \
            float hold[2] = { __bfloat162float(hv.x) + __bfloat162float(lv.x), \
                              __bfloat162float(hv.y) + __bfloat162float(lv.y) }; \
            _Pragma("unroll") \
            for (int cc = 0; cc < 2; ++cc) { \
                const int k = rh * 2 + cc; \
                float r = sigf(fmaf(s_i, acci[0][k], fmaf(s_h, acch[0][k], bR[cc]))); \
                float z = sigf(fmaf(s_i, acci[1][k], fmaf(s_h, acch[1][k], bZ[cc]))); \
                float n = tanhf(fmaf(s_i, acci[2][k], bNi[cc]) \
                                + r * fmaf(s_h, acch[2][k], bNh[cc])); \
                res[rh][cc] = (1.f - z) * n + z * hold[cc]; \
            } \
        } \
    } while (0)

    #define STORE_H(HHI, HLO) do { \
        _Pragma("unroll") \
        for (int rh = 0; rh < 2; ++rh) { \
            const size_t off = (size_t)(b_r + rh * 8) * 256 + jb; \
            __nv_bfloat16 hi0 = __float2bfloat16(res[rh][0]); \
            __nv_bfloat16 hi1 = __float2bfloat16(res[rh][1]); \
            float lo0 = res[rh][0] - __bfloat162float(hi0); \
            float lo1 = res[rh][1] - __bfloat162float(hi1); \
            __nv_bfloat162 hp; hp.x = hi0; hp.y = hi1; \
            *(u32*)((HHI) + off) = *(u32*)&hp; \
            *(u32*)((HLO) + off) = pkbf(lo0, lo1); \
        } \
    } while (0)

    if (!isL2) {
        // =============== Layer 1: phases 0..511 ===============
        ISSUE_SRC(g_xhi, g_xlo, 0);   // x chunks for p=0
        for (int p = 0; p < SEQ; ++p) {
            const int rs = p & 3;      // h1 ring slot holding h1(p)
            // wait: peers produced h1(p); L2 consumed h1(p-3) (ring reuse)
            ctr_wait2(ctr1, 16 * p, ctr2, 16 * (p - 3));
            ISSUE_SRC(g_h1hi[rs], g_h1lo[rs], 2);

            float acci[3][4] = {}, acch[3][4] = {};
            DO_CHUNK(0, 3);
            DO_CHUNK(1, 2);
            DO_CHUNK(2, 1);
            DO_CHUNK(3, 0);

            float res[2][2];
            GATE_EPI();
            const int ws = (p + 1) & 3;
            STORE_H(g_h1hi[ws], g_h1lo[ws]);

            ctr_arrive(ctr1);
            if (p + 1 < SEQ)
                ISSUE_SRC(g_xhi + (size_t)(p + 1) * 65536,
                          g_xlo + (size_t)(p + 1) * 65536, 0);
        }
    } else {
        // =============== Layer 2: phases 1..512 ===============
        for (int p = 1; p <= SEQ; ++p) {
            const int rs = p & 3;      // h1 ring slot holding h1(p)
            const int par = p & 1;     // h2 slot holding h2(p-1)
            // wait: L1 produced h1(p); peers produced h2(p-1)
            ctr_wait2(ctr1, 16 * p, ctr2, 16 * (p - 1));
            ISSUE_SRC(g_h1hi[rs], g_h1lo[rs], 0);
            ISSUE_SRC(g_h2hi[par], g_h2lo[par], 2);

            float acci[3][4] = {}, acch[3][4] = {};
            DO_CHUNK(0, 3);
            DO_CHUNK(1, 2);
            DO_CHUNK(2, 1);
            DO_CHUNK(3, 0);

            float res[2][2];
            GATE_EPI();
            if (p == SEQ) {
                *(float2*)(out + (size_t)b_r * 256 + jb) = make_float2(res[0][0], res[0][1]);
                *(float2*)(out + (size_t)(b_r + 8) * 256 + jb) = make_float2(res[1][0], res[1][1]);
            } else {
                STORE_H(g_h2hi[par ^ 1], g_h2lo[par ^ 1]);
            }
            ctr_arrive(ctr2);
        }
    }
}

// ---------------- host launch ----------------
extern "C" void kernel_launch(void* const* d_in, const int* in_sizes, int n_in,
                              void* d_out, int out_size) {
    (void)in_sizes; (void)n_in; (void)out_size;
    const float* x     = (const float*)d_in[0];
    const float* h1    = (const float*)d_in[1];
    const float* h2    = (const float*)d_in[2];
    const float* w_ih1 = (const float*)d_in[3];
    const float* w_hh1 = (const float*)d_in[4];
    const float* b_ih1 = (const float*)d_in[5];
    const float* b_hh1 = (const float*)d_in[6];
    const float* w_ih2 = (const float*)d_in[7];
    const float* w_hh2 = (const float*)d_in[8];
    const float* b_ih2 = (const float*)d_in[9];
    const float* b_hh2 = (const float*)d_in[10];
    float* out = (float*)d_out;

    cudaFuncSetAttribute(k_main, cudaFuncAttributeMaxDynamicSharedMemorySize, SMEM_BYTES);

    k_init<<<256, 256>>>(h1, h2);
    k_scales<<<4, 512>>>(w_ih1, w_hh1, w_ih2, w_hh2);
    k_pack<<<512, 256>>>(w_ih1, w_hh1, w_ih2, w_hh2);
    k_convx<<<32768, 256>>>(x);
    k_main<<<128, 256, SMEM_BYTES>>>(b_ih1, b_hh1, b_ih2, b_hh2, out);
}

// round 13
// speedup vs baseline: 1.1767x; 1.1767x over previous
#include <cuda_runtime.h>
#include <cuda_bf16.h>
#include <math.h>
#include <stdint.h>

#define SEQ 512

typedef unsigned int u32;
typedef unsigned long long u64;

// ---------------- device globals (no cudaMalloc allowed) ----------------
// quantized integer-valued weights (bf16-exact), layout gW[k*768 + c], c = gate*256 + j
__device__ float gW1x[256 * 768];
__device__ float gW1h[256 * 768];
__device__ float gW2i[256 * 768];
__device__ float gW2h[256 * 768];

// activations as bf16 hi/lo planes, [b][k] row-major
__device__ __nv_bfloat16 g_xhi[(size_t)SEQ * 65536];
__device__ __nv_bfloat16 g_xlo[(size_t)SEQ * 65536];
// h(m) stored in slot m&1
__device__ __nv_bfloat16 g_h1hi[2][65536];
__device__ __nv_bfloat16 g_h1lo[2][65536];
__device__ __nv_bfloat16 g_h2hi[2][65536];
__device__ __nv_bfloat16 g_h2lo[2][65536];

__device__ float g_scale[4];
// per-bt-group progress counters (one cache line each)
__device__ unsigned g_ctr[8 * 32];

// ---------------- helpers ----------------
__device__ __forceinline__ u32 smem_u32(const void* p) {
    u32 a;
    asm("{ .reg .u64 t; cvta.to.shared.u64 t, %1; cvt.u32.u64 %0, t; }" : "=r"(a) : "l"(p));
    return a;
}

#define LDMATRIX4(r, a) \
    asm volatile("ldmatrix.sync.aligned.m8n8.x4.shared.b16 {%0,%1,%2,%3}, [%4];" \
        : "=r"((r)[0]), "=r"((r)[1]), "=r"((r)[2]), "=r"((r)[3]) : "r"(a))

#define MMA16816(d, a, b0, b1) \
    asm volatile("mma.sync.aligned.m16n8k16.row.col.f32.bf16.bf16.f32 " \
        "{%0,%1,%2,%3}, {%4,%5,%6,%7}, {%8,%9}, {%0,%1,%2,%3};" \
        : "+f"((d)[0]), "+f"((d)[1]), "+f"((d)[2]), "+f"((d)[3]) \
        : "r"((a)[0]), "r"((a)[1]), "r"((a)[2]), "r"((a)[3]), "r"(b0), "r"(b1))

#define LDS128R(r0, r1, r2, r3, a) \
    asm volatile("ld.shared.v4.b32 {%0,%1,%2,%3}, [%4];" \
        : "=r"(r0), "=r"(r1), "=r"(r2), "=r"(r3) : "r"(a))

#define LDS32(r0, a) \
    asm volatile("ld.shared.b32 %0, [%1];" : "=r"(r0) : "r"(a))

#define CPA16(dst, src) \
    asm volatile("cp.async.cg.shared.global [%0], [%1], 16;" :: "r"(dst), "l"(src) : "memory")
#define CPA_COMMIT() asm volatile("cp.async.commit_group;" ::: "memory")
#define CPA_WAIT(N)  asm volatile("cp.async.wait_group %0;" :: "n"(N) : "memory")

__device__ __forceinline__ u32 pkbf(float x, float y) {
    __nv_bfloat162 t = __floats2bfloat162_rn(x, y);
    return *(u32*)&t;
}

__device__ __forceinline__ float sigf(float x) { return 1.f / (1.f + expf(-x)); }

// ---------------- setup kernels ----------------
__global__ void k_init(const float* __restrict__ h1, const float* __restrict__ h2) {
    int i = blockIdx.x * blockDim.x + threadIdx.x;
    if (i < 256) g_ctr[i] = 0u;
    if (i < 65536) {
        float v1 = h1[i], v2 = h2[i];
        __nv_bfloat16 a = __float2bfloat16(v1);
        g_h1hi[0][i] = a;                                  // h1(0) -> slot 0
        g_h1lo[0][i] = __float2bfloat16(v1 - __bfloat162float(a));
        __nv_bfloat16 b = __float2bfloat16(v2);
        g_h2hi[0][i] = b;                                  // h2(0) -> slot 0
        g_h2lo[0][i] = __float2bfloat16(v2 - __bfloat162float(b));
    }
}

__global__ void k_scales(const float* __restrict__ w0, const float* __restrict__ w1,
                         const float* __restrict__ w2, const float* __restrict__ w3) {
    const float* w = (blockIdx.x == 0) ? w0 : (blockIdx.x == 1) ? w1
                   : (blockIdx.x == 2) ? w2 : w3;
    const int n = 768 * 256;
    float m = 0.f;
    for (int i = threadIdx.x; i < n; i += blockDim.x) m = fmaxf(m, fabsf(w[i]));
    __shared__ float sm[512];
    sm[threadIdx.x] = m;
    __syncthreads();
    for (int s = blockDim.x >> 1; s > 0; s >>= 1) {
        if (threadIdx.x < s) sm[threadIdx.x] = fmaxf(sm[threadIdx.x], sm[threadIdx.x + s]);
        __syncthreads();
    }
    if (threadIdx.x == 0) g_scale[blockIdx.x] = sm[0] / 127.0f;
}

// gW[k*768 + c] = rint(W[c*256 + k] / s)   (c = gate*256 + j; |v| <= 127, bf16-exact)
__global__ void k_pack(const float* __restrict__ wih1, const float* __restrict__ whh1,
                       const float* __restrict__ wih2, const float* __restrict__ whh2) {
    const float s0 = g_scale[0], s1 = g_scale[1], s2 = g_scale[2], s3 = g_scale[3];
    const int N = 256 * 768;
    for (int i = blockIdx.x * blockDim.x + threadIdx.x; i < N;
         i += gridDim.x * blockDim.x) {
        int k = i / 768, c = i - k * 768;
        int off = c * 256 + k;
        gW1x[i] = rintf(wih1[off] / s0);
        gW1h[i] = rintf(whh1[off] / s1);
        gW2i[i] = rintf(wih2[off] / s2);
        gW2h[i] = rintf(whh2[off] / s3);
    }
}

// x -> bf16 hi/lo planes
__global__ void k_convx(const float* __restrict__ x) {
    size_t i = ((size_t)blockIdx.x * blockDim.x + threadIdx.x) * 4;
    if (i >= (size_t)SEQ * 65536) return;
    float4 v = *(const float4*)(x + i);
    float vv[4] = {v.x, v.y, v.z, v.w};
    __nv_bfloat16 hi[4], lo[4];
    #pragma unroll
    for (int r = 0; r < 4; ++r) {
        hi[r] = __float2bfloat16(vv[r]);
        lo[r] = __float2bfloat16(vv[r] - __bfloat162float(hi[r]));
    }
    *(uint2*)(g_xhi + i) = *(uint2*)hi;
    *(uint2*)(g_xlo + i) = *(uint2*)lo;
}

// ---------------- main persistent kernel ----------------
// 128 CTAs x 256 threads = 8 bt-groups x 16 jt. Per CTA: M=32 rows x N=48 (gate-major),
// BOTH layers: warps 0-3 = L1 phase s (h1(s+1)), warps 4-7 = L2 phase s (h2(s)).
// A planes (bf16, stride 528): [0]=x-hi [1]=x-lo [2]=h1-hi [3]=h1-lo [4]=h2-hi [5]=h2-lo.
// B frag stream: [wg*2+src][tile(6)][kpair(8)][lane(32)][16B] per-wg weights.
#define S_BF   1024
#define S_A    99328
#define A_STR  528
#define A_PL   16896
#define SMEM_BYTES 200704

__global__ void __launch_bounds__(256) k_main(
    const float* __restrict__ b_ih1, const float* __restrict__ b_hh1,
    const float* __restrict__ b_ih2, const float* __restrict__ b_hh2,
    float* __restrict__ out)
{
    extern __shared__ char smem[];
    const u32 sbase = smem_u32(smem);
    float* sBias = (float*)smem;

    const int tid = threadIdx.x;
    const int ln = tid & 31, w = tid >> 5;
    const int wg = w >> 2;               // 0 = layer1, 1 = layer2
    const int wm = w & 1;                // 16-row half
    const int wn = (w >> 1) & 1;         // j-half of 8
    const int bid = blockIdx.x;
    const int bt = bid >> 4;             // 0..7
    const int jt = bid & 15;
    const int b0 = bt * 32;
    const int j0 = jt * 16;

    unsigned* ctr = &g_ctr[bt * 32];

    // ---- one-time: B fragment stream (both layers; paired 16B per 2 ksteps)
    {
        const int sB = w & 1;
        const int ksh = (w >> 1) & 1;
        const float* Ws;
        if (wg == 0) Ws = sB ? gW1h : gW1x;
        else         Ws = sB ? gW2h : gW2i;
        const int n = ln >> 2, kp4 = ln & 3;
        for (int ks = ksh * 8; ks < ksh * 8 + 8; ++ks) {
            #pragma unroll
            for (int tt = 0; tt < 6; ++tt) {
                int j = j0 + (tt & 1) * 8 + n;
                int c = (tt >> 1) * 256 + j;
                int k0 = ks * 16 + kp4 * 2;
                u32 f0 = pkbf(Ws[(size_t)k0 * 768 + c], Ws[(size_t)(k0 + 1) * 768 + c]);
                u32 f1 = pkbf(Ws[(size_t)(k0 + 8) * 768 + c], Ws[(size_t)(k0 + 9) * 768 + c]);
                u32 ad = sbase + S_BF
                       + (u32)(((((wg * 2 + sB) * 6 + tt) * 8 + (ks >> 1)) * 32 + ln) * 16)
                       + (u32)((ks & 1) * 8);
                asm volatile("st.shared.v2.b32 [%0], {%1,%2};" :: "r"(ad), "r"(f0), "r"(f1) : "memory");
            }
        }
    }
    if (tid < 32) {
        int lj = tid & 15;
        int j = j0 + lj;
        const float* bi = (tid < 16) ? b_ih1 : b_ih2;
        const float* bh = (tid < 16) ? b_hh1 : b_hh2;
        sBias[tid * 4 + 0] = bi[j] + bh[j];
        sBias[tid * 4 + 1] = bi[j + 256] + bh[j + 256];
        sBias[tid * 4 + 2] = bi[j + 512];
        sBias[tid * 4 + 3] = bh[j + 512];
    }
    const float s_i = (wg == 0) ? g_scale[0] : g_scale[2];
    const float s_h = (wg == 0) ? g_scale[1] : g_scale[3];
    __syncthreads();

    // per-lane constants
    const int jb = j0 + wn * 8 + (ln & 3) * 2;      // global j of col pair
    const int b_r = b0 + wm * 16 + (ln >> 2);       // global batch row
    const int jl = wg * 16 + wn * 8 + (ln & 3) * 2; // bias index base
    float bR[2], bZ[2], bNi[2], bNh[2];
    #pragma unroll
    for (int cc = 0; cc < 2; ++cc) {
        bR[cc]  = sBias[(jl + cc) * 4 + 0];
        bZ[cc]  = sBias[(jl + cc) * 4 + 1];
        bNi[cc] = sBias[(jl + cc) * 4 + 2];
        bNh[cc] = sBias[(jl + cc) * 4 + 3];
    }
    const u32 a_base = sbase + S_A + (u32)(wm * 16 + (ln & 15)) * A_STR + (u32)((ln >> 4) * 16);
    // h_old planes: L1 -> h1 (planes 2,3); L2 -> h2 (planes 4,5)
    const u32 h_base = sbase + S_A + (u32)(2 + wg * 2) * A_PL
                     + (u32)(wm * 16 + (ln >> 2)) * A_STR + (u32)(jb * 2);
    // staging map: 4 threads per plane-row
    const int st_pr  = tid >> 2;
    const int st_q   = st_pr >> 5;        // plane within pair
    const int st_row = st_pr & 31;
    const int st_seg = (tid & 3) * 64;

    #define STAGE(PHI, PLO, PB, KH) do { \
        const char* _s = (const char*)(st_q ? (const void*)(PLO) : (const void*)(PHI)) \
                       + (size_t)(b0 + st_row) * 512 + (KH) * 256 + st_seg; \
        u32 _d = sbase + S_A + (u32)((PB) + st_q) * A_PL + (u32)st_row * A_STR \
               + (u32)((KH) * 256 + st_seg); \
        CPA16(_d, _s); CPA16(_d + 16, _s + 16); \
        CPA16(_d + 32, _s + 32); CPA16(_d + 48, _s + 48); \
    } while (0)

    for (int sph = 0; sph <= SEQ; ++sph) {
        const bool act1 = (sph < SEQ);       // L1 computes h1(sph+1)
        const bool act2 = (sph >= 1);        // L2 computes h2(sph)
        const bool myact = wg ? act2 : act1;

        // ---- G0,G1: x(sph) both k-halves (ready before the wait)
        if (act1) {
            const __nv_bfloat16* xh = g_xhi + (size_t)sph * 65536;
            const __nv_bfloat16* xl = g_xlo + (size_t)sph * 65536;
            STAGE(xh, xl, 0, 0); CPA_COMMIT();
            STAGE(xh, xl, 0, 1); CPA_COMMIT();
        } else { CPA_COMMIT(); CPA_COMMIT(); }

        // ---- group-local wait: all 16 CTAs finished phase sph-1
        if (sph > 0) {
            if (tid == 0) {
                unsigned tgt = 16u * (unsigned)sph;
                while (*(volatile unsigned*)ctr < tgt) { }
                __threadfence();
            }
            __syncthreads();
        }

        // ---- G2..G5: h1(sph) slot sph&1, h2(sph-1) slot (sph-1)&1
        {
            const int s1 = sph & 1, s2 = (sph - 1) & 1;
            STAGE(g_h1hi[s1], g_h1lo[s1], 2, 0); CPA_COMMIT();
            STAGE(g_h2hi[s2], g_h2lo[s2], 4, 0); CPA_COMMIT();
            STAGE(g_h1hi[s1], g_h1lo[s1], 2, 1); CPA_COMMIT();
            STAGE(g_h2hi[s2], g_h2lo[s2], 4, 1); CPA_COMMIT();
        }

        // ---- MMA: 2 k-halves; per half: 2 sources x 4 kpairs
        float acci[3][4] = {}, acch[3][4] = {};
        #pragma unroll
        for (int kh = 0; kh < 2; ++kh) {
            if (kh == 0) { CPA_WAIT(2); } else { CPA_WAIT(0); }
            __syncthreads();
            if (myact) {
                #pragma unroll
                for (int s01 = 0; s01 < 2; ++s01) {
                    const u32 apl0 = a_base + (u32)(wg * 2 + s01 * 2) * A_PL;
                    const u32 bb = sbase + S_BF
                                 + (u32)(((wg * 2 + s01) * 6) * 8 * 32 * 16);
                    #pragma unroll
                    for (int kp = 0; kp < 4; ++kp) {
                        const int kpg = kh * 4 + kp;
                        u32 aE[2][4], aO[2][4];
                        #pragma unroll
                        for (int q = 0; q < 2; ++q) {
                            LDMATRIX4(aE[q], apl0 + (u32)q * A_PL + (u32)(kpg * 64));
                            LDMATRIX4(aO[q], apl0 + (u32)q * A_PL + (u32)(kpg * 64 + 32));
                        }
                        #pragma unroll
                        for (int g = 0; g < 3; ++g) {
                            u32 f0, f1, f2, f3;
                            u32 bad = bb + (u32)((((g * 2 + wn) * 8 + kpg) * 32 + ln) * 16);
                            LDS128R(f0, f1, f2, f3, bad);
                            float* acc = s01 ? acch[g] : acci[g];
                            MMA16816(acc, aE[0], f0, f1);
                            MMA16816(acc, aE[1], f0, f1);
                            MMA16816(acc, aO[0], f2, f3);
                            MMA16816(acc, aO[1], f2, f3);
                        }
                    }
                }
            }
        }

        // ---- epilogue (active warps): gates in registers, h_old from staged planes
        if (myact) {
            float res[2][2];
            #pragma unroll
            for (int rh = 0; rh < 2; ++rh) {
                u32 hw, lw;
                LDS32(hw, h_base + (u32)(rh * 8) * A_STR);
                LDS32(lw, h_base + (u32)(rh * 8) * A_STR + A_PL);
                __nv_bfloat162 hv = *(__nv_bfloat162*)&hw;
                __nv_bfloat162 lv = *(__nv_bfloat162*)&lw;
                float hold[2] = { __bfloat162float(hv.x) + __bfloat162float(lv.x),
                                  __bfloat162float(hv.y) + __bfloat162float(lv.y) };
                #pragma unroll
                for (int cc = 0; cc < 2; ++cc) {
                    const int k = rh * 2 + cc;
                    float r = sigf(fmaf(s_i, acci[0][k], fmaf(s_h, acch[0][k], bR[cc])));
                    float z = sigf(fmaf(s_i, acci[1][k], fmaf(s_h, acch[1][k], bZ[cc])));
                    float n = tanhf(fmaf(s_i, acci[2][k], bNi[cc])
                                    + r * fmaf(s_h, acch[2][k], bNh[cc]));
                    res[rh][cc] = (1.f - z) * n + z * hold[cc];
                }
            }
            if (wg == 1 && sph == SEQ) {
                *(float2*)(out + (size_t)b_r * 256 + jb) = make_float2(res[0][0], res[0][1]);
                *(float2*)(out + (size_t)(b_r + 8) * 256 + jb) = make_float2(res[1][0], res[1][1]);
            } else {
                __nv_bfloat16* hhi;
                __nv_bfloat16* hlo;
                if (wg == 0) { const int ws = (sph + 1) & 1; hhi = g_h1hi[ws]; hlo = g_h1lo[ws]; }
                else         { const int ws = sph & 1;       hhi = g_h2hi[ws]; hlo = g_h2lo[ws]; }
                #pragma unroll
                for (int rh = 0; rh < 2; ++rh) {
                    const size_t off = (size_t)(b_r + rh * 8) * 256 + jb;
                    __nv_bfloat16 hi0 = __float2bfloat16(res[rh][0]);
                    __nv_bfloat16 hi1 = __float2bfloat16(res[rh][1]);
                    float lo0 = res[rh][0] - __bfloat162float(hi0);
                    float lo1 = res[rh][1] - __bfloat162float(hi1);
                    __nv_bfloat162 hp; hp.x = hi0; hp.y = hi1;
                    *(u32*)(hhi + off) = *(u32*)&hp;
                    *(u32*)(hlo + off) = pkbf(lo0, lo1);
                }
            }
        }

        // ---- arrive
        __syncthreads();
        if (tid == 0) {
            __threadfence();
            atomicAdd(ctr, 1u);
        }
    }
    #undef STAGE
}

// ---------------- host launch ----------------
extern "C" void kernel_launch(void* const* d_in, const int* in_sizes, int n_in,
                              void* d_out, int out_size) {
    (void)in_sizes; (void)n_in; (void)out_size;
    const float* x     = (const float*)d_in[0];
    const float* h1    = (const float*)d_in[1];
    const float* h2    = (const float*)d_in[2];
    const float* w_ih1 = (const float*)d_in[3];
    const float* w_hh1 = (const float*)d_in[4];
    const float* b_ih1 = (const float*)d_in[5];
    const float* b_hh1 = (const float*)d_in[6];
    const float* w_ih2 = (const float*)d_in[7];
    const float* w_hh2 = (const float*)d_in[8];
    const float* b_ih2 = (const float*)d_in[9];
    const float* b_hh2 = (const float*)d_in[10];
    float* out = (float*)d_out;

    cudaFuncSetAttribute(k_main, cudaFuncAttributeMaxDynamicSharedMemorySize, SMEM_BYTES);

    k_init<<<256, 256>>>(h1, h2);
    k_scales<<<4, 512>>>(w_ih1, w_hh1, w_ih2, w_hh2);
    k_pack<<<512, 256>>>(w_ih1, w_hh1, w_ih2, w_hh2);
    k_convx<<<32768, 256>>>(x);
    k_main<<<128, 256, SMEM_BYTES>>>(b_ih1, b_hh1, b_ih2, b_hh2, out);
}